// round 8
// baseline (speedup 1.0000x reference)
#include <cuda_runtime.h>
#include <cstdint>

#define Bn 16
#define Ln 4096
#define Cn 1024
#define Kn 16
#define NEG_INF (__int_as_float(0xff800000))

typedef unsigned long long ull;

// ---------------- global scratch ----------------
__device__ float g_scores[(size_t)Bn * Kn * Ln];            // 4MB
__device__ ull   g_w2[(size_t)Bn * Ln * Kn];                // 8MB dup-packed weights

// ---------------- helpers ----------------
__device__ __forceinline__ ull fma2(ull a, ull b, ull c) {
    ull d;
    asm("fma.rn.f32x2 %0, %1, %2, %3;" : "=l"(d) : "l"(a), "l"(b), "l"(c));
    return d;
}
__device__ __forceinline__ float2 unpack2(ull v) {
    float2 f;
    f.x = __uint_as_float((unsigned)(v & 0xffffffffULL));
    f.y = __uint_as_float((unsigned)(v >> 32));
    return f;
}
__device__ __forceinline__ ull pack2(float a, float b) {
    ull v;
    asm("mov.b64 %0, {%1, %2};" : "=l"(v) : "f"(a), "f"(b));
    return v;
}
__device__ __forceinline__ uint32_t smem_u32(const void* p) {
    return (uint32_t)__cvta_generic_to_shared(p);
}
__device__ __forceinline__ void cp16(uint32_t dst, const void* src) {
    asm volatile("cp.async.cg.shared.global [%0], [%1], 16;" :: "r"(dst), "l"(src));
}
__device__ __forceinline__ void cp_commit() {
    asm volatile("cp.async.commit_group;");
}
template <int N>
__device__ __forceinline__ void cp_wait() {
    asm volatile("cp.async.wait_group %0;" :: "n"(N) : "memory");
}
// load 8 consecutive floats as 4 f32x2 words
__device__ __forceinline__ void load8(ull* xv, const float* p) {
    ulonglong2 a = *(const ulonglong2*)p;
    ulonglong2 b = *(const ulonglong2*)(p + 4);
    xv[0] = a.x; xv[1] = a.y; xv[2] = b.x; xv[3] = b.y;
}

// =================== Pass 1: scores = x @ q^T ===================
// grid 1024 = 16 b x 64 chunks(64 l); 256 thr = 8 warps x 8 l
// smem: q 64KB + scores 4KB + mask
#define P1_QS   0
#define P1_SS   65536
#define P1_MK   69632
#define P1_SMEM 69888

extern "C" __global__ void __launch_bounds__(256, 2)
pass1_scores(const float* __restrict__ x, const int* __restrict__ mask,
             const float* __restrict__ q) {
    extern __shared__ char smem[];
    const uint32_t sb = smem_u32(smem);
    float* qs = (float*)smem;
    float* s_s = (float*)(smem + P1_SS);        // [16 k][64 l]
    int* mask_s = (int*)(smem + P1_MK);

    const int tid = threadIdx.x;
    const int w = tid >> 5, lane = tid & 31;
    const int cg = lane & 7, lg = lane >> 3;    // cg: c-octet, lg: l-pair group
    const int b = blockIdx.x >> 6;
    const int l0 = (blockIdx.x & 63) * 64;

    // stage q (64KB) via cp.async, once
#pragma unroll
    for (int i = 0; i < 16; ++i) {
        int idx = tid + i * 256;                // float4 index, 4096 total
        cp16(sb + P1_QS + idx * 16, q + idx * 4);
    }
    cp_commit();
    if (tid < 64) mask_s[tid] = mask[b * Ln + l0 + tid];

    // x rows this thread owns (2 consecutive l)
    const float* xr0 = x + ((size_t)b * Ln + l0 + w * 8 + lg * 2) * Cn;
    const float* xr1 = xr0 + Cn;

    ull xbuf[2][2][4];                          // [buf][row][4 f32x2]
    load8(xbuf[0][0], xr0 + cg * 8);
    load8(xbuf[0][1], xr1 + cg * 8);
    load8(xbuf[1][0], xr0 + 64 + cg * 8);
    load8(xbuf[1][1], xr1 + 64 + cg * 8);

    ull acc[2][16];
#pragma unroll
    for (int j = 0; j < 2; ++j)
#pragma unroll
        for (int k = 0; k < 16; ++k) acc[j][k] = 0ULL;

    cp_wait<0>();
    __syncthreads();

    for (int t = 0; t < 16; ++t) {
        ull (*xv)[4] = xbuf[t & 1];
#pragma unroll
        for (int k = 0; k < 16; ++k) {
            const ulonglong2* qp =
                (const ulonglong2*)(qs + k * Cn + t * 64 + cg * 8);
            ulonglong2 qa = qp[0], qb = qp[1];
#pragma unroll
            for (int j = 0; j < 2; ++j) {
                acc[j][k] = fma2(xv[j][0], qa.x, acc[j][k]);
                acc[j][k] = fma2(xv[j][1], qa.y, acc[j][k]);
                acc[j][k] = fma2(xv[j][2], qb.x, acc[j][k]);
                acc[j][k] = fma2(xv[j][3], qb.y, acc[j][k]);
            }
        }
        if (t < 14) {
            load8(xbuf[t & 1][0], xr0 + (t + 2) * 64 + cg * 8);
            load8(xbuf[t & 1][1], xr1 + (t + 2) * 64 + cg * 8);
        }
    }

    // fold + 3-shfl cg reduction
#pragma unroll
    for (int j = 0; j < 2; ++j)
#pragma unroll
        for (int k = 0; k < 16; ++k) {
            float2 f = unpack2(acc[j][k]);
            float s = f.x + f.y;
            s += __shfl_xor_sync(0xffffffffu, s, 1);
            s += __shfl_xor_sync(0xffffffffu, s, 2);
            s += __shfl_xor_sync(0xffffffffu, s, 4);
            if (cg == 0)
                s_s[k * 64 + w * 8 + lg * 2 + j] = s;
        }
    __syncthreads();

    // coalesced masked write
    {
        const int k = tid >> 4, li = (tid & 15) * 4;
        float4 v = *(float4*)&s_s[k * 64 + li];
        float4 o;
        o.x = mask_s[li]     ? v.x * 0.03125f : NEG_INF;
        o.y = mask_s[li + 1] ? v.y * 0.03125f : NEG_INF;
        o.z = mask_s[li + 2] ? v.z * 0.03125f : NEG_INF;
        o.w = mask_s[li + 3] ? v.w * 0.03125f : NEG_INF;
        *(float4*)(g_scores + ((size_t)(b * Kn + k)) * Ln + l0 + li) = o;
    }
}

// =================== Pass 2: softmax + dup-packed weights ===================
extern "C" __global__ void __launch_bounds__(256)
pass2_softmax() {
    const int bk = blockIdx.x;
    const int b = bk >> 4, k = bk & 15;
    const int tid = threadIdx.x;
    const int wid = tid >> 5, lane = tid & 31;
    __shared__ float red[8];
    __shared__ float s_m, s_d;

    const float* sc = g_scores + (size_t)bk * Ln;
    float v[16];
    float m = NEG_INF;
#pragma unroll
    for (int i = 0; i < 16; ++i) {
        v[i] = sc[i * 256 + tid];
        m = fmaxf(m, v[i]);
    }
#pragma unroll
    for (int off = 16; off; off >>= 1)
        m = fmaxf(m, __shfl_xor_sync(0xffffffffu, m, off));
    if (lane == 0) red[wid] = m;
    __syncthreads();
    if (tid == 0) {
        float mm = red[0];
#pragma unroll
        for (int i = 1; i < 8; ++i) mm = fmaxf(mm, red[i]);
        s_m = mm;
    }
    __syncthreads();
    m = s_m;

    float e[16];
    float d = 0.f;
    if (m == NEG_INF) {
#pragma unroll
        for (int i = 0; i < 16; ++i) e[i] = 0.f;
    } else {
#pragma unroll
        for (int i = 0; i < 16; ++i) { e[i] = __expf(v[i] - m); d += e[i]; }
    }
#pragma unroll
    for (int off = 16; off; off >>= 1)
        d += __shfl_xor_sync(0xffffffffu, d, off);
    if (lane == 0) red[wid] = d;
    __syncthreads();
    if (tid == 0) {
        float dd = 0.f;
#pragma unroll
        for (int i = 0; i < 8; ++i) dd += red[i];
        s_d = dd;
    }
    __syncthreads();
    d = s_d;

    const float inv = (m == NEG_INF || d <= 0.f) ? 0.f : (1.0f / d);
    ull* wb = g_w2 + (size_t)b * Ln * Kn + k;
#pragma unroll
    for (int i = 0; i < 16; ++i) {
        float wv = e[i] * inv;
        wb[(size_t)(i * 256 + tid) * Kn] = pack2(wv, wv);
    }
}

// =================== Pass 3: out = W @ x ===================
// grid 512 = 16 b x 32 c-tiles(32 c); 256 thr = 8 cc(4c) x 32 lg
// smem: 3-slot w2 ring (16KB each)
#define P3_SLOT 16384
#define P3_SMEM 49152

extern "C" __global__ void __launch_bounds__(256, 2)
pass3_pooled(const float* __restrict__ x, float* __restrict__ out) {
    extern __shared__ char smem[];
    const uint32_t sb = smem_u32(smem);
    const int tid = threadIdx.x;
    const int cc = tid & 7, lg = tid >> 3;      // cc: c-chunk of 4, lg: 0..31
    const int b = blockIdx.x >> 5, ct = blockIdx.x & 31;
    const int c0 = ct * 32 + cc * 4;
    const float* xb = x + (size_t)b * Ln * Cn;
    const ull* wb = g_w2 + (size_t)b * Ln * Kn;

    // fill slot s with l-segment seg (128 l x 16 k ULL = 16KB)
    auto fill = [&](int seg, int slot) {
#pragma unroll
        for (int i = 0; i < 4; ++i) {
            int off = tid + i * 256;            // 16B units, 1024 total
            cp16(sb + slot * P3_SLOT + off * 16, wb + seg * 2048 + off * 2);
        }
    };
    fill(0, 0); cp_commit();
    fill(1, 1); cp_commit();

    ull acc[16][2];
#pragma unroll
    for (int k = 0; k < 16; ++k) { acc[k][0] = 0ULL; acc[k][1] = 0ULL; }

    for (int seg = 0; seg < 32; ++seg) {
        cp_wait<1>();            // segment 'seg' resident
        __syncthreads();         // all prior reads of slot (seg+2)%3 finished
        if (seg < 30) { fill(seg + 2, (seg + 2) % 3); cp_commit(); }

        // load this segment's 4 x rows upfront (MLP 4)
        float4 xv[4];
#pragma unroll
        for (int j = 0; j < 4; ++j)
            xv[j] = *(const float4*)(xb +
                     (size_t)(seg * 128 + j * 32 + lg) * Cn + c0);

        const ull* wslot = (const ull*)(smem + (seg % 3) * P3_SLOT);
#pragma unroll
        for (int j = 0; j < 4; ++j) {
            const int lrel = j * 32 + lg;
            const ulonglong2* wp = (const ulonglong2*)(wslot + lrel * 16);
            ull xlo = pack2(xv[j].x, xv[j].y);
            ull xhi = pack2(xv[j].z, xv[j].w);
#pragma unroll
            for (int p = 0; p < 8; ++p) {
                ulonglong2 wv = wp[p];          // k = 2p, 2p+1 (dup-packed)
                acc[2 * p][0]     = fma2(wv.x, xlo, acc[2 * p][0]);
                acc[2 * p][1]     = fma2(wv.x, xhi, acc[2 * p][1]);
                acc[2 * p + 1][0] = fma2(wv.y, xlo, acc[2 * p + 1][0]);
                acc[2 * p + 1][1] = fma2(wv.y, xhi, acc[2 * p + 1][1]);
            }
        }
    }

    // ---- epilogue: reduce over lg ----
    // stage 1: in-warp (4 lg per warp): shfl_xor 8, 16
#pragma unroll
    for (int k = 0; k < 16; ++k)
#pragma unroll
        for (int h = 0; h < 2; ++h) {
            float2 f = unpack2(acc[k][h]);
            f.x += __shfl_xor_sync(0xffffffffu, f.x, 8);
            f.y += __shfl_xor_sync(0xffffffffu, f.y, 8);
            f.x += __shfl_xor_sync(0xffffffffu, f.x, 16);
            f.y += __shfl_xor_sync(0xffffffffu, f.y, 16);
            acc[k][h] = pack2(f.x, f.y);
        }
    __syncthreads();             // everyone done reading w2 slots

    // stage 2: across 8 warps via smem
    float* s_r = (float*)smem;   // [8 w][16 k][32 c]
    const int w = tid >> 5, lane = tid & 31;
    if (lane < 8) {
#pragma unroll
        for (int k = 0; k < 16; ++k) {
            float2 f0 = unpack2(acc[k][0]);
            float2 f1 = unpack2(acc[k][1]);
            *(float4*)&s_r[w * 512 + k * 32 + lane * 4] =
                make_float4(f0.x, f0.y, f1.x, f1.y);
        }
    }
    __syncthreads();
    {
        const int o = tid * 2;               // 512 outputs
        const int k = o >> 5, c32 = o & 31;
        float s0 = 0.f, s1 = 0.f;
#pragma unroll
        for (int ww = 0; ww < 8; ++ww) {
            s0 += s_r[ww * 512 + k * 32 + c32];
            s1 += s_r[ww * 512 + k * 32 + c32 + 1];
        }
        *(float2*)(out + ((size_t)(b * Kn + k)) * Cn + ct * 32 + c32) =
            make_float2(s0, s1);
    }
}

extern "C" void kernel_launch(void* const* d_in, const int* in_sizes, int n_in,
                              void* d_out, int out_size) {
    const float* x  = (const float*)d_in[0];
    const int* mask = (const int*)d_in[1];
    const float* q  = (const float*)d_in[2];
    float* out      = (float*)d_out;

    cudaFuncSetAttribute(pass1_scores,
                         cudaFuncAttributeMaxDynamicSharedMemorySize, P1_SMEM);
    cudaFuncSetAttribute(pass3_pooled,
                         cudaFuncAttributeMaxDynamicSharedMemorySize, P3_SMEM);

    pass1_scores<<<1024, 256, P1_SMEM>>>(x, mask, q);
    pass2_softmax<<<Bn * Kn, 256>>>();
    pass3_pooled<<<512, 256, P3_SMEM>>>(x, out);
}

// round 9
// speedup vs baseline: 1.6350x; 1.6350x over previous
#include <cuda_runtime.h>
#include <math.h>

#define Bn 16
#define Ln 4096
#define Cn 1024
#define Kn 16
#define NSPLIT 32
#define CHUNK 128
#define THREADS 512
#define TC 128
#define NTILE 8
#define QSTRIDE 132
#define NEG_INF (__int_as_float(0xff800000))

typedef unsigned long long ull;

__device__ float g_acc[(size_t)Bn * NSPLIT * Kn * Cn];
__device__ float g_m[Bn * NSPLIT * Kn];
__device__ float g_d[Bn * NSPLIT * Kn];

__device__ __forceinline__ ull fma2(ull a, ull b, ull c) {
    ull d;
    asm("fma.rn.f32x2 %0, %1, %2, %3;" : "=l"(d) : "l"(a), "l"(b), "l"(c));
    return d;
}
__device__ __forceinline__ float2 unpack2(ull v) {
    float2 f;
    f.x = __uint_as_float((unsigned)(v & 0xffffffffULL));
    f.y = __uint_as_float((unsigned)(v >> 32));
    return f;
}
__device__ __forceinline__ ull pack2(float a, float b) {
    ull v;
    asm("mov.b64 %0, {%1, %2};" : "=l"(v) : "f"(a), "f"(b));
    return v;
}
__device__ __forceinline__ void cp_async16(unsigned int smem, const void* g) {
    asm volatile("cp.async.cg.shared.global [%0], [%1], 16;" :: "r"(smem), "l"(g));
}
__device__ __forceinline__ void cp_commit() {
    asm volatile("cp.async.commit_group;");
}
template <int N>
__device__ __forceinline__ void cp_wait() {
    asm volatile("cp.async.wait_group %0;" :: "n"(N) : "memory");
}

// SMEM byte offsets (combined-kernel map)
#define XS0   0
#define XS1   65536
#define QS0   131072                       // 16*132*4 = 8448 per buffer
#define QS1   (131072 + 8448)
#define SSOFF (131072 + 16896)             // scores [Kn][CHUNK] float (8KB)
#define W2OFF (SSOFF + Kn * CHUNK * 4)     // weights [64 lp][16 k] ull (8KB)
#define MKOFF (W2OFF + 64 * Kn * 8)        // mask [128] int
#define SMEM_TOTAL (MKOFF + CHUNK * 4)

extern "C" __global__ void __launch_bounds__(THREADS, 1)
pool_partial_kernel(const float* __restrict__ x,
                    const int* __restrict__ mask,
                    const float* __restrict__ q) {
    extern __shared__ char smem[];
    unsigned int smem_u32 = (unsigned int)__cvta_generic_to_shared(smem);
    float* s_s = (float*)(smem + SSOFF);
    int* mask_s = (int*)(smem + MKOFF);

    const int tid = threadIdx.x;
    const int w = tid >> 5;
    const int lane = tid & 31;
    const int cg = lane & 7;       // c-group within warp (round-2 layout)
    const int kg = lane >> 3;      // k-group (4 k's each)
    const int b = blockIdx.x / NSPLIT;
    const int split = blockIdx.x % NSPLIT;
    const int l0 = split * CHUNK;
    const float* xbase = x + ((size_t)b * Ln + l0) * Cn;

    // ---- prefetch tile 0 (x + q) ----
    {
        unsigned int xd = smem_u32 + XS0;
#pragma unroll
        for (int r = 0; r < 8; ++r) {
            int id = tid + THREADS * r;
            int row = id >> 5, c4 = id & 31;
            cp_async16(xd + row * 512 + c4 * 16,
                       xbase + (size_t)row * Cn + c4 * 4);
        }
        int qrow = tid >> 5, qc4 = tid & 31;
        cp_async16(smem_u32 + QS0 + qrow * (QSTRIDE * 4) + qc4 * 16,
                   q + qrow * Cn + qc4 * 4);
        cp_commit();
    }
    if (tid < CHUNK) mask_s[tid] = mask[b * Ln + l0 + tid];

    // round-2 Phase A: acc[8 l][4 k] f32x2
    ull acc[8][4];
#pragma unroll
    for (int a = 0; a < 8; ++a)
#pragma unroll
        for (int i = 0; i < 4; ++i) acc[a][i] = 0ULL;

    // ---------------- Phase A: tiled scores (round-2 verbatim) ----------------
    for (int t = 0; t < NTILE; ++t) {
        if (t < NTILE - 1) {
            const int tn = t + 1;
            unsigned int xd = smem_u32 + ((tn & 1) ? XS1 : XS0);
#pragma unroll
            for (int r = 0; r < 8; ++r) {
                int id = tid + THREADS * r;
                int row = id >> 5, c4 = id & 31;
                cp_async16(xd + row * 512 + c4 * 16,
                           xbase + (size_t)row * Cn + tn * TC + c4 * 4);
            }
            int qrow = tid >> 5, qc4 = tid & 31;
            cp_async16(smem_u32 + ((tn & 1) ? QS1 : QS0) + qrow * (QSTRIDE * 4) + qc4 * 16,
                       q + qrow * Cn + tn * TC + qc4 * 4);
            cp_commit();
            cp_wait<1>();
        } else {
            cp_wait<0>();
        }
        __syncthreads();

        const float* xs = (const float*)(smem + ((t & 1) ? XS1 : XS0));
        const float* qs = (const float*)(smem + ((t & 1) ? QS1 : QS0));

#pragma unroll
        for (int quad = 0; quad < 4; ++quad) {
            const int cof = cg * 4 + quad * 32;
            ulonglong2 qv[4];
#pragma unroll
            for (int i = 0; i < 4; ++i)
                qv[i] = *(const ulonglong2*)(qs + (kg * 4 + i) * QSTRIDE + cof);
#pragma unroll
            for (int j = 0; j < 8; ++j) {
                ulonglong2 xv = *(const ulonglong2*)(xs + (w * 8 + j) * TC + cof);
#pragma unroll
                for (int i = 0; i < 4; ++i) {
                    acc[j][i] = fma2(xv.x, qv[i].x, acc[j][i]);
                    acc[j][i] = fma2(xv.y, qv[i].y, acc[j][i]);
                }
            }
        }
        __syncthreads();
    }

    // ---- fold + 3-shfl cg reduction + masked write ----
    {
        const float scale = 0.03125f;
#pragma unroll
        for (int j = 0; j < 8; ++j)
#pragma unroll
            for (int i = 0; i < 4; ++i) {
                float2 f = unpack2(acc[j][i]);
                float s = f.x + f.y;
                s += __shfl_xor_sync(0xffffffffu, s, 1);
                s += __shfl_xor_sync(0xffffffffu, s, 2);
                s += __shfl_xor_sync(0xffffffffu, s, 4);
                if (cg == 0) {
                    const int l = w * 8 + j;
                    const int k = kg * 4 + i;
                    s_s[k * CHUNK + l] = mask_s[l] ? (s * scale) : NEG_INF;
                }
            }
    }
    __syncthreads();

    // ---------------- Phase B: softmax stats, warp w <-> k=w ----------------
    {
        const int k = w;   // 16 warps, one k each
        float v0 = s_s[k * CHUNK + lane];
        float v1 = s_s[k * CHUNK + lane + 32];
        float v2 = s_s[k * CHUNK + lane + 64];
        float v3 = s_s[k * CHUNK + lane + 96];
        float m = fmaxf(fmaxf(v0, v1), fmaxf(v2, v3));
#pragma unroll
        for (int off = 16; off; off >>= 1)
            m = fmaxf(m, __shfl_xor_sync(0xffffffffu, m, off));
        float e0, e1, e2, e3;
        if (m == NEG_INF) {
            e0 = e1 = e2 = e3 = 0.f;
        } else {
            e0 = __expf(v0 - m); e1 = __expf(v1 - m);
            e2 = __expf(v2 - m); e3 = __expf(v3 - m);
        }
        float d = e0 + e1 + e2 + e3;
#pragma unroll
        for (int off = 16; off; off >>= 1)
            d += __shfl_xor_sync(0xffffffffu, d, off);
        // l-pair packed weights: w2f[lp*32 + k*2 + (l&1)]
        float* w2f = (float*)(smem + W2OFF);
        {
            int l = lane;
            w2f[(l >> 1) * 32 + k * 2 + (l & 1)] = e0;
            l = lane + 32;
            w2f[(l >> 1) * 32 + k * 2 + (l & 1)] = e1;
            l = lane + 64;
            w2f[(l >> 1) * 32 + k * 2 + (l & 1)] = e2;
            l = lane + 96;
            w2f[(l >> 1) * 32 + k * 2 + (l & 1)] = e3;
        }
        if (lane == 0) {
            g_m[(b * NSPLIT + split) * Kn + k] = m;
            g_d[(b * NSPLIT + split) * Kn + k] = d;
        }
    }
    __syncthreads();

    // -------- Phase C: weighted accumulation, depth-4 LDG prefetch --------
    {
        const int c0 = tid * 2;   // thread owns a c-pair
        const ulonglong2* w2v = (const ulonglong2*)(smem + W2OFF);  // [lp][8 kp]
        ull a2[Kn][2];
#pragma unroll
        for (int k = 0; k < Kn; ++k) { a2[k][0] = 0ULL; a2[k][1] = 0ULL; }

        ull xb0[4], xb1[4];   // prefetch pipeline: rows 2lp, 2lp+1
#pragma unroll
        for (int i = 0; i < 4; ++i) {
            xb0[i] = *(const ull*)(xbase + (size_t)(2 * i) * Cn + c0);
            xb1[i] = *(const ull*)(xbase + (size_t)(2 * i + 1) * Cn + c0);
        }

#pragma unroll 4
        for (int lp = 0; lp < 64; ++lp) {
            const int sl = lp & 3;
            float2 fa = unpack2(xb0[sl]);
            float2 fb = unpack2(xb1[sl]);
            ull v0 = pack2(fa.x, fb.x);   // (x_l0[c0], x_l1[c0])
            ull v1 = pack2(fa.y, fb.y);   // (x_l0[c1], x_l1[c1])
            if (lp < 60) {
                xb0[sl] = *(const ull*)(xbase + (size_t)(2 * (lp + 4)) * Cn + c0);
                xb1[sl] = *(const ull*)(xbase + (size_t)(2 * (lp + 4) + 1) * Cn + c0);
            }
#pragma unroll
            for (int kp = 0; kp < 8; ++kp) {
                ulonglong2 wp = w2v[lp * 8 + kp];   // broadcast: 2 k's, l-pair packed
                a2[2 * kp][0]     = fma2(wp.x, v0, a2[2 * kp][0]);
                a2[2 * kp][1]     = fma2(wp.x, v1, a2[2 * kp][1]);
                a2[2 * kp + 1][0] = fma2(wp.y, v0, a2[2 * kp + 1][0]);
                a2[2 * kp + 1][1] = fma2(wp.y, v1, a2[2 * kp + 1][1]);
            }
        }
        float* ab = g_acc + ((size_t)(b * NSPLIT + split) * Kn) * Cn;
#pragma unroll
        for (int k = 0; k < Kn; ++k) {
            float2 r0 = unpack2(a2[k][0]);
            float2 r1 = unpack2(a2[k][1]);
            float2 o;
            o.x = r0.x + r0.y;   // fold l-pair
            o.y = r1.x + r1.y;
            *(float2*)(ab + (size_t)k * Cn + c0) = o;
        }
    }
}

// ---------------- Kernel 2: LSE merge ----------------
extern "C" __global__ void __launch_bounds__(128)
pool_reduce_kernel(float* __restrict__ out) {
    const int bk = blockIdx.x >> 2;
    const int b = bk >> 4;
    const int k = bk & 15;
    const int cq = blockIdx.x & 3;
    const int tid = threadIdx.x;

    __shared__ float coef[NSPLIT];
    if (tid < NSPLIT) {
        float m = g_m[(b * NSPLIT + tid) * Kn + k];
        float d = g_d[(b * NSPLIT + tid) * Kn + k];
        float M = m;
#pragma unroll
        for (int off = 16; off; off >>= 1)
            M = fmaxf(M, __shfl_xor_sync(0xffffffffu, M, off));
        float t = (m == NEG_INF) ? 0.f : d * __expf(m - M);
        float D = t;
#pragma unroll
        for (int off = 16; off; off >>= 1)
            D += __shfl_xor_sync(0xffffffffu, D, off);
        float c = 0.f;
        if (M != NEG_INF && D > 0.f)
            c = __expf(m - M) / D;
        coef[tid] = c;
    }
    __syncthreads();

    const int c0 = cq * 256 + tid * 2;
    ull o = 0ULL;
    const float* accb = g_acc + ((size_t)b * NSPLIT * Kn + k) * Cn;
#pragma unroll
    for (int s = 0; s < NSPLIT; ++s) {
        ull cs = pack2(coef[s], coef[s]);
        ull a = *(const ull*)(accb + (size_t)s * Kn * Cn + c0);
        o = fma2(cs, a, o);
    }
    *(ull*)(out + ((size_t)(b * Kn + k)) * Cn + c0) = o;
}

extern "C" void kernel_launch(void* const* d_in, const int* in_sizes, int n_in,
                              void* d_out, int out_size) {
    const float* x  = (const float*)d_in[0];
    const int* mask = (const int*)d_in[1];
    const float* q  = (const float*)d_in[2];
    float* out      = (float*)d_out;

    cudaFuncSetAttribute(pool_partial_kernel,
                         cudaFuncAttributeMaxDynamicSharedMemorySize, SMEM_TOTAL);
    pool_partial_kernel<<<Bn * NSPLIT, THREADS, SMEM_TOTAL>>>(x, mask, q);
    pool_reduce_kernel<<<Bn * Kn * 4, 128>>>(out);
}